// round 1
// baseline (speedup 1.0000x reference)
#include <cuda_runtime.h>
#include <math.h>

#define BATCH 8192
#define IN1   49
#define HID   256
#define NCOEF 13
#define KP1   688      // 49*14 = 686, padded to /16
#define K2    3584     // 256*14, already /16 and /32
#define OUT3  10

// ---- scratch (device globals; no allocation allowed) ----
__device__ float g_H0[BATCH * IN1];
__device__ float g_H [BATCH * HID];
__device__ float g_A [(size_t)BATCH * K2];   // reused for every layer's expanded acts
__device__ float g_W [K2 * HID];             // reused packed weights

// ---------------- avg_pool2d 4x4: (B,1,28,28) -> (B,49) ----------------
__global__ void pool_kernel(const float* __restrict__ x, float* __restrict__ H0) {
    int idx = blockIdx.x * blockDim.x + threadIdx.x;
    if (idx >= BATCH * IN1) return;
    int b = idx / 49, p = idx - b * 49;
    int r = p / 7, c = p - r * 7;
    const float* base = x + (size_t)b * 784 + (r * 4) * 28 + c * 4;
    float s = 0.f;
#pragma unroll
    for (int i = 0; i < 4; i++)
#pragma unroll
        for (int j = 0; j < 4; j++) s += base[i * 28 + j];
    H0[idx] = s * 0.0625f;
}

// ------- expand: H(B,in) -> A(B,KP) = [mish(x) | 13 cubic bspline basis per input] -------
__global__ void expand_kernel(const float* __restrict__ H, float* __restrict__ A,
                              int in, int KP) {
    int idx = blockIdx.x * blockDim.x + threadIdx.x;
    if (idx >= BATCH * in) return;
    int b = idx / in, i = idx - b * in;
    float xv = H[idx];
    float* row = A + (size_t)b * KP;

    // mish(x) = x * tanh(softplus(x)), stable softplus
    float sp = fmaxf(xv, 0.f) + log1pf(expf(-fabsf(xv)));
    row[i] = xv * tanhf(sp);

    // Cox-de Boor, replicating reference exactly (knots t_j = -2 + 0.4*(j-3), j=0..16)
    const float h = 0.4f;
    float Bv[16];
#pragma unroll
    for (int j = 0; j < 16; j++) {
        float t0 = -2.0f + h * (float)(j - 3);
        float t1 = -2.0f + h * (float)(j - 2);
        Bv[j] = (xv >= t0 && xv < t1) ? 1.0f : 0.0f;
    }
#pragma unroll
    for (int d = 1; d <= 3; d++) {
        float inv = 1.0f / (h * (float)d);
#pragma unroll
        for (int j = 0; j < 16 - 3; j++) {       // upper bound 13 covers all d (extra iters harmless? no)
            // need j < 16-d; handled below
            if (j < 16 - d) {
                float tj   = -2.0f + h * (float)(j - 3);
                float tjd1 = -2.0f + h * (float)(j - 3 + d + 1);
                Bv[j] = (xv - tj) * inv * Bv[j] + (tjd1 - xv) * inv * Bv[j + 1];
            }
        }
        // elements j in [16-d, 16) are stale but never read at higher d for j<16-(d+1)... 
        // (safe: each level d only reads Bv[0..16-d], which were just written/valid)
        if (d < 3) {
            // also update the tail entries needed by next level: j in [13, 16-d)
            for (int j = 13; j < 16 - d; j++) {
                float tj   = -2.0f + h * (float)(j - 3);
                float tjd1 = -2.0f + h * (float)(j - 3 + d + 1);
                Bv[j] = (xv - tj) * inv * Bv[j] + (tjd1 - xv) * inv * Bv[j + 1];
            }
        }
    }
    float* srow = row + in + i * NCOEF;
#pragma unroll
    for (int g = 0; g < NCOEF; g++) srow[g] = Bv[g];
}

// zero the K..KP pad columns (layer 1 only)
__global__ void zeropad_kernel(float* __restrict__ A, int K, int KP) {
    int pad = KP - K;
    int idx = blockIdx.x * blockDim.x + threadIdx.x;
    if (idx >= BATCH * pad) return;
    int b = idx / pad, c = K + (idx - b * pad);
    A[(size_t)b * KP + c] = 0.f;
}

// pack W(KP,out): rows [0,in) = sb ; rows [in, in*14) = coef*sp ; pad rows = 0
__global__ void buildW_kernel(const float* __restrict__ coef, const float* __restrict__ sb,
                              const float* __restrict__ spc, float* __restrict__ W,
                              int in, int out, int KP) {
    int idx = blockIdx.x * blockDim.x + threadIdx.x;
    if (idx >= KP * out) return;
    int r = idx / out, o = idx - r * out;
    float v = 0.f;
    if (r < in) {
        v = sb[r * out + o];
    } else if (r < in * 14) {
        int q = r - in;
        int i = q / 13, g = q - i * 13;
        v = coef[(size_t)(i * out + o) * 13 + g] * spc[i * out + o];
    }
    W[idx] = v;
}

// ---------------- SGEMM: C(M,N) = A(M,K) @ W(K,N) + bias ; M%128==0, N%128==0, K%16==0 ----------------
__global__ __launch_bounds__(256)
void sgemm_kernel(const float* __restrict__ A, const float* __restrict__ W,
                  const float* __restrict__ bias, float* __restrict__ C,
                  int N, int K) {
    __shared__ float As[16][128];   // [k][m]
    __shared__ float Bs[16][128];   // [k][n]
    int tid = threadIdx.x;
    int bm = blockIdx.y * 128;
    int bn = blockIdx.x * 128;
    int tx = tid & 15, ty = tid >> 4;

    float acc[8][8];
#pragma unroll
    for (int i = 0; i < 8; i++)
#pragma unroll
        for (int j = 0; j < 8; j++) acc[i][j] = 0.f;

    int aRow = tid >> 2;     // + u*64
    int aC4  = tid & 3;
    int bRow = tid >> 5;     // + u*8
    int bC4  = tid & 31;

    for (int k0 = 0; k0 < K; k0 += 16) {
#pragma unroll
        for (int u = 0; u < 2; u++) {
            int row = aRow + u * 64;
            float4 v = *reinterpret_cast<const float4*>(
                A + (size_t)(bm + row) * K + k0 + aC4 * 4);
            As[aC4 * 4 + 0][row] = v.x;
            As[aC4 * 4 + 1][row] = v.y;
            As[aC4 * 4 + 2][row] = v.z;
            As[aC4 * 4 + 3][row] = v.w;
        }
#pragma unroll
        for (int u = 0; u < 2; u++) {
            int kr = bRow + u * 8;
            float4 v = *reinterpret_cast<const float4*>(
                W + (size_t)(k0 + kr) * N + bn + bC4 * 4);
            *reinterpret_cast<float4*>(&Bs[kr][bC4 * 4]) = v;
        }
        __syncthreads();
#pragma unroll
        for (int kk = 0; kk < 16; kk++) {
            float a[8], b[8];
#pragma unroll
            for (int i = 0; i < 8; i++) a[i] = As[kk][ty * 8 + i];
#pragma unroll
            for (int j = 0; j < 8; j++) b[j] = Bs[kk][tx * 8 + j];
#pragma unroll
            for (int i = 0; i < 8; i++)
#pragma unroll
                for (int j = 0; j < 8; j++) acc[i][j] = fmaf(a[i], b[j], acc[i][j]);
        }
        __syncthreads();
    }
#pragma unroll
    for (int i = 0; i < 8; i++) {
        int row = bm + ty * 8 + i;
#pragma unroll
        for (int j = 0; j < 8; j++) {
            int col = bn + tx * 8 + j;
            C[(size_t)row * N + col] = acc[i][j] + bias[col];
        }
    }
}

// ---------------- layer3: (B,3584)@(3584,10) + bias, fused log_softmax ----------------
__global__ __launch_bounds__(128)
void layer3_kernel(const float* __restrict__ A, const float* __restrict__ W,
                   const float* __restrict__ bias, float* __restrict__ out) {
    __shared__ float At[128][33];     // padded: stride 33 -> conflict-free column reads
    __shared__ float Ws[32 * 10];
    int t = threadIdx.x;
    int r0 = blockIdx.x * 128;
    float acc[10];
#pragma unroll
    for (int o = 0; o < 10; o++) acc[o] = 0.f;

    for (int k0 = 0; k0 < K2; k0 += 32) {
#pragma unroll
        for (int u = 0; u < 8; u++) {
            int f4 = u * 128 + t;
            int row = f4 >> 3, c4 = f4 & 7;
            float4 v = *reinterpret_cast<const float4*>(
                A + (size_t)(r0 + row) * K2 + k0 + c4 * 4);
            At[row][c4 * 4 + 0] = v.x;
            At[row][c4 * 4 + 1] = v.y;
            At[row][c4 * 4 + 2] = v.z;
            At[row][c4 * 4 + 3] = v.w;
        }
        for (int w = t; w < 320; w += 128)
            Ws[w] = W[(size_t)(k0 + w / 10) * 10 + (w % 10)];
        __syncthreads();
#pragma unroll
        for (int kk = 0; kk < 32; kk++) {
            float a = At[t][kk];
#pragma unroll
            for (int o = 0; o < 10; o++) acc[o] = fmaf(a, Ws[kk * 10 + o], acc[o]);
        }
        __syncthreads();
    }
#pragma unroll
    for (int o = 0; o < 10; o++) acc[o] += bias[o];
    float m = acc[0];
#pragma unroll
    for (int o = 1; o < 10; o++) m = fmaxf(m, acc[o]);
    float s = 0.f;
#pragma unroll
    for (int o = 0; o < 10; o++) s += expf(acc[o] - m);
    float ls = logf(s) + m;
    int row = r0 + t;
#pragma unroll
    for (int o = 0; o < 10; o++) out[(size_t)row * 10 + o] = acc[o] - ls;
}

extern "C" void kernel_launch(void* const* d_in, const int* in_sizes, int n_in,
                              void* d_out, int out_size) {
    const float* x     = (const float*)d_in[0];
    const float* coef1 = (const float*)d_in[1];
    const float* sb1   = (const float*)d_in[2];
    const float* sp1   = (const float*)d_in[3];
    const float* b1    = (const float*)d_in[4];
    const float* coef2 = (const float*)d_in[5];
    const float* sb2   = (const float*)d_in[6];
    const float* sp2   = (const float*)d_in[7];
    const float* b2    = (const float*)d_in[8];
    const float* coef3 = (const float*)d_in[9];
    const float* sb3   = (const float*)d_in[10];
    const float* sp3   = (const float*)d_in[11];
    const float* b3    = (const float*)d_in[12];
    float* out = (float*)d_out;

    float *H0, *H, *A, *W;
    cudaGetSymbolAddress((void**)&H0, g_H0);
    cudaGetSymbolAddress((void**)&H,  g_H);
    cudaGetSymbolAddress((void**)&A,  g_A);
    cudaGetSymbolAddress((void**)&W,  g_W);

    pool_kernel<<<(BATCH * IN1 + 255) / 256, 256>>>(x, H0);

    // ---- layer 1: in=49, K=686 -> KP=688 ----
    expand_kernel<<<(BATCH * IN1 + 255) / 256, 256>>>(H0, A, IN1, KP1);
    zeropad_kernel<<<(BATCH * (KP1 - 686) + 255) / 256, 256>>>(A, 686, KP1);
    buildW_kernel<<<(KP1 * HID + 255) / 256, 256>>>(coef1, sb1, sp1, W, IN1, HID, KP1);
    dim3 g1(HID / 128, BATCH / 128);
    sgemm_kernel<<<g1, 256>>>(A, W, b1, H, HID, KP1);

    // ---- layer 2: in=256, K=3584 ----
    expand_kernel<<<(BATCH * HID + 255) / 256, 256>>>(H, A, HID, K2);
    buildW_kernel<<<(K2 * HID + 255) / 256, 256>>>(coef2, sb2, sp2, W, HID, HID, K2);
    sgemm_kernel<<<g1, 256>>>(A, W, b2, H, HID, K2);

    // ---- layer 3: in=256, K=3584, out=10, fused log_softmax ----
    expand_kernel<<<(BATCH * HID + 255) / 256, 256>>>(H, A, HID, K2);
    buildW_kernel<<<(K2 * OUT3 + 255) / 256, 256>>>(coef3, sb3, sp3, W, HID, OUT3, K2);
    layer3_kernel<<<BATCH / 128, 128>>>(A, W, b3, out);
}

// round 2
// speedup vs baseline: 1.0064x; 1.0064x over previous
#include <cuda_runtime.h>
#include <math.h>

#define BATCH 8192
#define IN1   49
#define HID   256
#define NCOEF 13
#define KP1   688      // 49*14 = 686, padded to /16
#define K2    3584     // 256*14, already /16 and /32
#define OUT3  10

// ---- scratch (device globals; no allocation allowed) ----
__device__ float g_H0[BATCH * IN1];
__device__ float g_H [BATCH * HID];
__device__ float g_A [(size_t)BATCH * K2];   // reused for every layer's expanded acts
__device__ float g_W [K2 * HID];             // reused packed weights

// ---------------- avg_pool2d 4x4: (B,1,28,28) -> (B,49) ----------------
__global__ void pool_kernel(const float* __restrict__ x, float* __restrict__ H0) {
    int idx = blockIdx.x * blockDim.x + threadIdx.x;
    if (idx >= BATCH * IN1) return;
    int b = idx / 49, p = idx - b * 49;
    int r = p / 7, c = p - r * 7;
    const float* base = x + (size_t)b * 784 + (r * 4) * 28 + c * 4;
    float s = 0.f;
#pragma unroll
    for (int i = 0; i < 4; i++)
#pragma unroll
        for (int j = 0; j < 4; j++) s += base[i * 28 + j];
    H0[idx] = s * 0.0625f;
}

// ------- expand: H(B,in) -> A(B,KP) = [mish(x) | 13 cubic bspline basis per input] -------
__global__ void expand_kernel(const float* __restrict__ H, float* __restrict__ A,
                              int in, int KP) {
    int idx = blockIdx.x * blockDim.x + threadIdx.x;
    if (idx >= BATCH * in) return;
    int b = idx / in, i = idx - b * in;
    float xv = H[idx];
    float* row = A + (size_t)b * KP;

    // mish(x) = x * tanh(softplus(x)), stable softplus
    float sp = fmaxf(xv, 0.f) + log1pf(expf(-fabsf(xv)));
    row[i] = xv * tanhf(sp);

    // Cox-de Boor, replicating reference exactly (knots t_j = -2 + 0.4*(j-3), j=0..16)
    const float h = 0.4f;
    float Bv[16];
#pragma unroll
    for (int j = 0; j < 16; j++) {
        float t0 = -2.0f + h * (float)(j - 3);
        float t1 = -2.0f + h * (float)(j - 2);
        Bv[j] = (xv >= t0 && xv < t1) ? 1.0f : 0.0f;
    }
#pragma unroll
    for (int d = 1; d <= 3; d++) {
        float inv = 1.0f / (h * (float)d);
#pragma unroll
        for (int j = 0; j < 16 - 3; j++) {       // upper bound 13 covers all d (extra iters harmless? no)
            // need j < 16-d; handled below
            if (j < 16 - d) {
                float tj   = -2.0f + h * (float)(j - 3);
                float tjd1 = -2.0f + h * (float)(j - 3 + d + 1);
                Bv[j] = (xv - tj) * inv * Bv[j] + (tjd1 - xv) * inv * Bv[j + 1];
            }
        }
        // elements j in [16-d, 16) are stale but never read at higher d for j<16-(d+1)... 
        // (safe: each level d only reads Bv[0..16-d], which were just written/valid)
        if (d < 3) {
            // also update the tail entries needed by next level: j in [13, 16-d)
            for (int j = 13; j < 16 - d; j++) {
                float tj   = -2.0f + h * (float)(j - 3);
                float tjd1 = -2.0f + h * (float)(j - 3 + d + 1);
                Bv[j] = (xv - tj) * inv * Bv[j] + (tjd1 - xv) * inv * Bv[j + 1];
            }
        }
    }
    float* srow = row + in + i * NCOEF;
#pragma unroll
    for (int g = 0; g < NCOEF; g++) srow[g] = Bv[g];
}

// zero the K..KP pad columns (layer 1 only)
__global__ void zeropad_kernel(float* __restrict__ A, int K, int KP) {
    int pad = KP - K;
    int idx = blockIdx.x * blockDim.x + threadIdx.x;
    if (idx >= BATCH * pad) return;
    int b = idx / pad, c = K + (idx - b * pad);
    A[(size_t)b * KP + c] = 0.f;
}

// pack W(KP,out): rows [0,in) = sb ; rows [in, in*14) = coef*sp ; pad rows = 0
__global__ void buildW_kernel(const float* __restrict__ coef, const float* __restrict__ sb,
                              const float* __restrict__ spc, float* __restrict__ W,
                              int in, int out, int KP) {
    int idx = blockIdx.x * blockDim.x + threadIdx.x;
    if (idx >= KP * out) return;
    int r = idx / out, o = idx - r * out;
    float v = 0.f;
    if (r < in) {
        v = sb[r * out + o];
    } else if (r < in * 14) {
        int q = r - in;
        int i = q / 13, g = q - i * 13;
        v = coef[(size_t)(i * out + o) * 13 + g] * spc[i * out + o];
    }
    W[idx] = v;
}

// ---------------- SGEMM: C(M,N) = A(M,K) @ W(K,N) + bias ; M%128==0, N%128==0, K%16==0 ----------------
__global__ __launch_bounds__(256)
void sgemm_kernel(const float* __restrict__ A, const float* __restrict__ W,
                  const float* __restrict__ bias, float* __restrict__ C,
                  int N, int K) {
    __shared__ float As[16][128];   // [k][m]
    __shared__ float Bs[16][128];   // [k][n]
    int tid = threadIdx.x;
    int bm = blockIdx.y * 128;
    int bn = blockIdx.x * 128;
    int tx = tid & 15, ty = tid >> 4;

    float acc[8][8];
#pragma unroll
    for (int i = 0; i < 8; i++)
#pragma unroll
        for (int j = 0; j < 8; j++) acc[i][j] = 0.f;

    int aRow = tid >> 2;     // + u*64
    int aC4  = tid & 3;
    int bRow = tid >> 5;     // + u*8
    int bC4  = tid & 31;

    for (int k0 = 0; k0 < K; k0 += 16) {
#pragma unroll
        for (int u = 0; u < 2; u++) {
            int row = aRow + u * 64;
            float4 v = *reinterpret_cast<const float4*>(
                A + (size_t)(bm + row) * K + k0 + aC4 * 4);
            As[aC4 * 4 + 0][row] = v.x;
            As[aC4 * 4 + 1][row] = v.y;
            As[aC4 * 4 + 2][row] = v.z;
            As[aC4 * 4 + 3][row] = v.w;
        }
#pragma unroll
        for (int u = 0; u < 2; u++) {
            int kr = bRow + u * 8;
            float4 v = *reinterpret_cast<const float4*>(
                W + (size_t)(k0 + kr) * N + bn + bC4 * 4);
            *reinterpret_cast<float4*>(&Bs[kr][bC4 * 4]) = v;
        }
        __syncthreads();
#pragma unroll
        for (int kk = 0; kk < 16; kk++) {
            float a[8], b[8];
#pragma unroll
            for (int i = 0; i < 8; i++) a[i] = As[kk][ty * 8 + i];
#pragma unroll
            for (int j = 0; j < 8; j++) b[j] = Bs[kk][tx * 8 + j];
#pragma unroll
            for (int i = 0; i < 8; i++)
#pragma unroll
                for (int j = 0; j < 8; j++) acc[i][j] = fmaf(a[i], b[j], acc[i][j]);
        }
        __syncthreads();
    }
#pragma unroll
    for (int i = 0; i < 8; i++) {
        int row = bm + ty * 8 + i;
#pragma unroll
        for (int j = 0; j < 8; j++) {
            int col = bn + tx * 8 + j;
            C[(size_t)row * N + col] = acc[i][j] + bias[col];
        }
    }
}

// ---------------- layer3: (B,3584)@(3584,10) + bias, fused log_softmax ----------------
__global__ __launch_bounds__(128)
void layer3_kernel(const float* __restrict__ A, const float* __restrict__ W,
                   const float* __restrict__ bias, float* __restrict__ out) {
    __shared__ float At[128][33];     // padded: stride 33 -> conflict-free column reads
    __shared__ float Ws[32 * 10];
    int t = threadIdx.x;
    int r0 = blockIdx.x * 128;
    float acc[10];
#pragma unroll
    for (int o = 0; o < 10; o++) acc[o] = 0.f;

    for (int k0 = 0; k0 < K2; k0 += 32) {
#pragma unroll
        for (int u = 0; u < 8; u++) {
            int f4 = u * 128 + t;
            int row = f4 >> 3, c4 = f4 & 7;
            float4 v = *reinterpret_cast<const float4*>(
                A + (size_t)(r0 + row) * K2 + k0 + c4 * 4);
            At[row][c4 * 4 + 0] = v.x;
            At[row][c4 * 4 + 1] = v.y;
            At[row][c4 * 4 + 2] = v.z;
            At[row][c4 * 4 + 3] = v.w;
        }
        for (int w = t; w < 320; w += 128)
            Ws[w] = W[(size_t)(k0 + w / 10) * 10 + (w % 10)];
        __syncthreads();
#pragma unroll
        for (int kk = 0; kk < 32; kk++) {
            float a = At[t][kk];
#pragma unroll
            for (int o = 0; o < 10; o++) acc[o] = fmaf(a, Ws[kk * 10 + o], acc[o]);
        }
        __syncthreads();
    }
#pragma unroll
    for (int o = 0; o < 10; o++) acc[o] += bias[o];
    float m = acc[0];
#pragma unroll
    for (int o = 1; o < 10; o++) m = fmaxf(m, acc[o]);
    float s = 0.f;
#pragma unroll
    for (int o = 0; o < 10; o++) s += expf(acc[o] - m);
    float ls = logf(s) + m;
    int row = r0 + t;
#pragma unroll
    for (int o = 0; o < 10; o++) out[(size_t)row * 10 + o] = acc[o] - ls;
}

extern "C" void kernel_launch(void* const* d_in, const int* in_sizes, int n_in,
                              void* d_out, int out_size) {
    const float* x     = (const float*)d_in[0];
    const float* coef1 = (const float*)d_in[1];
    const float* sb1   = (const float*)d_in[2];
    const float* sp1   = (const float*)d_in[3];
    const float* b1    = (const float*)d_in[4];
    const float* coef2 = (const float*)d_in[5];
    const float* sb2   = (const float*)d_in[6];
    const float* sp2   = (const float*)d_in[7];
    const float* b2    = (const float*)d_in[8];
    const float* coef3 = (const float*)d_in[9];
    const float* sb3   = (const float*)d_in[10];
    const float* sp3   = (const float*)d_in[11];
    const float* b3    = (const float*)d_in[12];
    float* out = (float*)d_out;

    float *H0, *H, *A, *W;
    cudaGetSymbolAddress((void**)&H0, g_H0);
    cudaGetSymbolAddress((void**)&H,  g_H);
    cudaGetSymbolAddress((void**)&A,  g_A);
    cudaGetSymbolAddress((void**)&W,  g_W);

    pool_kernel<<<(BATCH * IN1 + 255) / 256, 256>>>(x, H0);

    // ---- layer 1: in=49, K=686 -> KP=688 ----
    expand_kernel<<<(BATCH * IN1 + 255) / 256, 256>>>(H0, A, IN1, KP1);
    zeropad_kernel<<<(BATCH * (KP1 - 686) + 255) / 256, 256>>>(A, 686, KP1);
    buildW_kernel<<<(KP1 * HID + 255) / 256, 256>>>(coef1, sb1, sp1, W, IN1, HID, KP1);
    dim3 g1(HID / 128, BATCH / 128);
    sgemm_kernel<<<g1, 256>>>(A, W, b1, H, HID, KP1);

    // ---- layer 2: in=256, K=3584 ----
    expand_kernel<<<(BATCH * HID + 255) / 256, 256>>>(H, A, HID, K2);
    buildW_kernel<<<(K2 * HID + 255) / 256, 256>>>(coef2, sb2, sp2, W, HID, HID, K2);
    sgemm_kernel<<<g1, 256>>>(A, W, b2, H, HID, K2);

    // ---- layer 3: in=256, K=3584, out=10, fused log_softmax ----
    expand_kernel<<<(BATCH * HID + 255) / 256, 256>>>(H, A, HID, K2);
    buildW_kernel<<<(K2 * OUT3 + 255) / 256, 256>>>(coef3, sb3, sp3, W, HID, OUT3, K2);
    layer3_kernel<<<BATCH / 128, 128>>>(A, W, b3, out);
}

// round 5
// speedup vs baseline: 1.2568x; 1.2488x over previous
#include <cuda_runtime.h>
#include <cuda_bf16.h>
#include <cstdint>
#include <math.h>

#define BATCH 8192
#define IN1   49
#define HID   256
#define NCOEF 13
#define KP1   704      // 49*14 = 686, padded to 64-multiple
#define K2    3584     // 256*14
#define OUT3  10

// ================= helpers (baseline PTX only: sm_80-era features) =================
__device__ __forceinline__ uint32_t smem_to_u32(const void* p) {
    uint32_t a;
    asm("{ .reg .u64 t; cvta.to.shared.u64 t, %1; cvt.u32.u64 %0, t; }" : "=r"(a) : "l"(p));
    return a;
}

#define CP16(dst, src) \
    asm volatile("cp.async.cg.shared.global [%0], [%1], 16;" :: "r"(dst), "l"(src) : "memory")
#define CP_COMMIT() asm volatile("cp.async.commit_group;" ::: "memory")
#define CP_WAIT1()  asm volatile("cp.async.wait_group 1;" ::: "memory")
#define CP_WAIT0()  asm volatile("cp.async.wait_group 0;" ::: "memory")

#define LDSM4(r, addr) \
    asm volatile("ldmatrix.sync.aligned.m8n8.x4.shared.b16 {%0,%1,%2,%3}, [%4];" \
        : "=r"((r)[0]), "=r"((r)[1]), "=r"((r)[2]), "=r"((r)[3]) : "r"(addr))

#define MMA_BF16(d, a, b0, b1) \
    asm volatile("mma.sync.aligned.m16n8k16.row.col.f32.bf16.bf16.f32 " \
        "{%0,%1,%2,%3},{%4,%5,%6,%7},{%8,%9},{%0,%1,%2,%3};" \
        : "+f"((d)[0]), "+f"((d)[1]), "+f"((d)[2]), "+f"((d)[3]) \
        : "r"((a)[0]), "r"((a)[1]), "r"((a)[2]), "r"((a)[3]), "r"(b0), "r"(b1))

// ================= scratch =================
__device__ float         g_H0[BATCH * IN1];
__device__ float         g_H [BATCH * HID];
__device__ __nv_bfloat16 g_Ah[(size_t)BATCH * K2];
__device__ __nv_bfloat16 g_Al[(size_t)BATCH * K2];
__device__ __nv_bfloat16 g_Wh[HID * K2];
__device__ __nv_bfloat16 g_Wl[HID * K2];
__device__ float         g_W3[K2 * OUT3];

// ================= pool =================
__global__ void pool_kernel(const float* __restrict__ x, float* __restrict__ H0) {
    int idx = blockIdx.x * blockDim.x + threadIdx.x;
    if (idx >= BATCH * IN1) return;
    int b = idx / 49, p = idx - b * 49;
    int r = p / 7, c = p - r * 7;
    const float* base = x + (size_t)b * 784 + (r * 4) * 28 + c * 4;
    float s = 0.f;
#pragma unroll
    for (int i = 0; i < 4; i++)
#pragma unroll
        for (int j = 0; j < 4; j++) s += base[i * 28 + j];
    H0[idx] = s * 0.0625f;
}

// ================= expand (fp32 -> bf16 hi/lo split) =================
__device__ __forceinline__ void store_hl(__nv_bfloat16* Ah, __nv_bfloat16* Al, size_t off, float v) {
    __nv_bfloat16 hi = __float2bfloat16(v);
    Ah[off] = hi;
    Al[off] = __float2bfloat16(v - __bfloat162float(hi));
}

__global__ void expand_kernel(const float* __restrict__ H, __nv_bfloat16* __restrict__ Ah,
                              __nv_bfloat16* __restrict__ Al, int in, int KP) {
    int idx = blockIdx.x * blockDim.x + threadIdx.x;
    if (idx >= BATCH * in) return;
    int b = idx / in, i = idx - b * in;
    float xv = H[idx];
    size_t base = (size_t)b * KP;

    float sp = fmaxf(xv, 0.f) + log1pf(expf(-fabsf(xv)));
    store_hl(Ah, Al, base + i, xv * tanhf(sp));

    const float h = 0.4f;
    float Bv[16];
#pragma unroll
    for (int j = 0; j < 16; j++) {
        float t0 = -2.0f + h * (float)(j - 3);
        float t1 = -2.0f + h * (float)(j - 2);
        Bv[j] = (xv >= t0 && xv < t1) ? 1.0f : 0.0f;
    }
#pragma unroll
    for (int d = 1; d <= 3; d++) {
        float inv = 1.0f / (h * (float)d);
#pragma unroll
        for (int j = 0; j < 16 - 3; j++) {
            if (j < 16 - d) {
                float tj   = -2.0f + h * (float)(j - 3);
                float tjd1 = -2.0f + h * (float)(j - 3 + d + 1);
                Bv[j] = (xv - tj) * inv * Bv[j] + (tjd1 - xv) * inv * Bv[j + 1];
            }
        }
        if (d < 3) {
            for (int j = 13; j < 16 - d; j++) {
                float tj   = -2.0f + h * (float)(j - 3);
                float tjd1 = -2.0f + h * (float)(j - 3 + d + 1);
                Bv[j] = (xv - tj) * inv * Bv[j] + (tjd1 - xv) * inv * Bv[j + 1];
            }
        }
    }
    size_t sroff = base + in + (size_t)i * NCOEF;
#pragma unroll
    for (int g = 0; g < NCOEF; g++) store_hl(Ah, Al, sroff + g, Bv[g]);
}

// zero pad cols [686, 704) of layer-1 A
__global__ void zeropad_kernel(__nv_bfloat16* __restrict__ Ah, __nv_bfloat16* __restrict__ Al) {
    int idx = blockIdx.x * blockDim.x + threadIdx.x;
    const int pad = KP1 - 686;
    if (idx >= BATCH * pad) return;
    int b = idx / pad, c = 686 + (idx - b * pad);
    __nv_bfloat16 z = __float2bfloat16(0.f);
    Ah[(size_t)b * KP1 + c] = z;
    Al[(size_t)b * KP1 + c] = z;
}

// pack W^T (N rows, KP cols, K-major) as bf16 hi/lo
__global__ void buildWt_kernel(const float* __restrict__ coef, const float* __restrict__ sb_,
                               const float* __restrict__ sp_, __nv_bfloat16* __restrict__ Wh,
                               __nv_bfloat16* __restrict__ Wl, int in, int out, int KP) {
    int idx = blockIdx.x * blockDim.x + threadIdx.x;
    if (idx >= out * KP) return;
    int n = idx / KP, k = idx - n * KP;
    float v = 0.f;
    if (k < in) {
        v = sb_[k * out + n];
    } else if (k < in * 14) {
        int q = k - in;
        int i = q / 13, g = q - i * 13;
        v = coef[((size_t)i * out + n) * 13 + g] * sp_[i * out + n];
    }
    __nv_bfloat16 hi = __float2bfloat16(v);
    Wh[idx] = hi;
    Wl[idx] = __float2bfloat16(v - __bfloat162float(hi));
}

// pack layer-3 W (K rows, 10 cols) as fp32
__global__ void buildW3_kernel(const float* __restrict__ coef, const float* __restrict__ sb_,
                               const float* __restrict__ sp_, float* __restrict__ W) {
    int idx = blockIdx.x * blockDim.x + threadIdx.x;
    if (idx >= K2 * OUT3) return;
    int r = idx / OUT3, o = idx - r * OUT3;
    float v;
    if (r < HID) {
        v = sb_[r * OUT3 + o];
    } else {
        int q = r - HID;
        int i = q / 13, g = q - i * 13;
        v = coef[((size_t)i * OUT3 + o) * 13 + g] * sp_[i * OUT3 + o];
    }
    W[idx] = v;
}

// ================= HMMA GEMM: C(M,Nc) = (Ah+Al)(M,K) @ (Wh+Wl)^T + bias =================
// 128x128 tile, K-chunk 32 bf16, cp.async double buffer, mma.sync m16n8k16, 3-term split.
#define ASTRIDE     80                 // 64B data + 16B pad: conflict-free ldmatrix
#define MAT_BYTES   (128 * ASTRIDE)    // 10240
#define STAGE_BYTES (4 * MAT_BYTES)    // 40960
#define SMEM_GEMM   (2 * STAGE_BYTES + 512)

__global__ __launch_bounds__(256)
void gemm_kernel(const __nv_bfloat16* __restrict__ Ah, const __nv_bfloat16* __restrict__ Al,
                 const __nv_bfloat16* __restrict__ Wh, const __nv_bfloat16* __restrict__ Wl,
                 const float* __restrict__ bias, float* __restrict__ C, int K, int Nc) {
    extern __shared__ char smem[];
    uint32_t sbase = smem_to_u32(smem);
    float* bsm = (float*)(smem + 2 * STAGE_BYTES);
    int tid = threadIdx.x, lane = tid & 31, wid = tid >> 5;
    int bm = blockIdx.y * 128, bn = blockIdx.x * 128;
    if (tid < 128) bsm[tid] = bias[bn + tid];

    const size_t strideA = (size_t)K * 2;   // bytes per row
    const char* pAh = (const char*)Ah;
    const char* pAl = (const char*)Al;
    const char* pWh = (const char*)Wh;
    const char* pWl = (const char*)Wl;

    float acc[4][4][4];
#pragma unroll
    for (int i = 0; i < 4; i++)
#pragma unroll
        for (int j = 0; j < 4; j++)
#pragma unroll
            for (int q = 0; q < 4; q++) acc[i][j][q] = 0.f;

    // warp tile: 64 (M) x 32 (N)
    int wm = (wid & 1) * 64, wn = (wid >> 1) * 32;
    // ldmatrix lane addressing
    int a_row = lane & 15, a_hi = lane >> 4;              // A: rows m0..m0+15, k-half
    int bg = lane >> 3;
    int b_row = ((bg >> 1) << 3) + (lane & 7);            // B: n within 16-row group
    int b_hi = bg & 1;                                    // k-half

    int nch = K >> 5;

    // --- loader (2 (row,chunk) pairs per matrix per thread) ---
#define LOAD_CHUNK(stage, c) do { \
        size_t kb = (size_t)(c) * 64; \
        uint32_t sst = sbase + (stage) * STAGE_BYTES; \
        _Pragma("unroll") \
        for (int u = 0; u < 2; u++) { \
            int idx = u * 256 + tid; \
            int row = idx >> 2, ch = idx & 3; \
            uint32_t soff = row * ASTRIDE + ch * 16; \
            size_t ga = (size_t)(bm + row) * strideA + kb + ch * 16; \
            size_t gb = (size_t)(bn + row) * strideA + kb + ch * 16; \
            CP16(sst + soff,                 pAh + ga); \
            CP16(sst + MAT_BYTES + soff,     pAl + ga); \
            CP16(sst + 2 * MAT_BYTES + soff, pWh + gb); \
            CP16(sst + 3 * MAT_BYTES + soff, pWl + gb); \
        } \
    } while (0)

    LOAD_CHUNK(0, 0);
    CP_COMMIT();

    for (int c = 0; c < nch; c++) {
        if (c + 1 < nch) {
            LOAD_CHUNK((c + 1) & 1, c + 1);
            CP_COMMIT();
            CP_WAIT1();
        } else {
            CP_WAIT0();
        }
        __syncthreads();

        uint32_t base = sbase + (c & 1) * STAGE_BYTES;
        uint32_t aAh = base, aAl = base + MAT_BYTES;
        uint32_t aBh = base + 2 * MAT_BYTES, aBl = base + 3 * MAT_BYTES;

#pragma unroll
        for (int kk = 0; kk < 2; kk++) {          // two k16 steps per chunk
            int kch = kk * 2;                     // chunk-of-16B base within row
            uint32_t ahf[4][4], alf[4][4], bhf[2][4], blf[2][4];
#pragma unroll
            for (int mt = 0; mt < 4; mt++) {
                uint32_t ao = (uint32_t)(wm + mt * 16 + a_row) * ASTRIDE + (kch + a_hi) * 16;
                LDSM4(ahf[mt], aAh + ao);
                LDSM4(alf[mt], aAl + ao);
            }
#pragma unroll
            for (int np = 0; np < 2; np++) {
                uint32_t bo = (uint32_t)(wn + np * 16 + b_row) * ASTRIDE + (kch + b_hi) * 16;
                LDSM4(bhf[np], aBh + bo);
                LDSM4(blf[np], aBl + bo);
            }
#pragma unroll
            for (int mt = 0; mt < 4; mt++)
#pragma unroll
                for (int nt = 0; nt < 4; nt++) {
                    int np = nt >> 1, s = (nt & 1) * 2;
                    MMA_BF16(acc[mt][nt], ahf[mt], bhf[np][s], bhf[np][s + 1]);
                    MMA_BF16(acc[mt][nt], ahf[mt], blf[np][s], blf[np][s + 1]);
                    MMA_BF16(acc[mt][nt], alf[mt], bhf[np][s], bhf[np][s + 1]);
                }
        }
        __syncthreads();
    }
#undef LOAD_CHUNK

    // epilogue: +bias, float2 stores
#pragma unroll
    for (int mt = 0; mt < 4; mt++) {
        int r0 = bm + wm + mt * 16 + (lane >> 2);
#pragma unroll
        for (int nt = 0; nt < 4; nt++) {
            int cl = wn + nt * 8 + (lane & 3) * 2;
            float bz0 = bsm[cl], bz1 = bsm[cl + 1];
            float2 v0, v1;
            v0.x = acc[mt][nt][0] + bz0;  v0.y = acc[mt][nt][1] + bz1;
            v1.x = acc[mt][nt][2] + bz0;  v1.y = acc[mt][nt][3] + bz1;
            *(float2*)(C + (size_t)r0 * Nc + bn + cl)       = v0;
            *(float2*)(C + (size_t)(r0 + 8) * Nc + bn + cl) = v1;
        }
    }
}

// ================= layer3: (B,3584)@(3584,10) + bias, fused log_softmax, split-K =================
__global__ __launch_bounds__(256)
void layer3_kernel(const __nv_bfloat16* __restrict__ Ah, const __nv_bfloat16* __restrict__ Al,
                   const float* __restrict__ W3, const float* __restrict__ bias,
                   float* __restrict__ out) {
    __shared__ float At[2][128][33];
    __shared__ float Ws[2][320];
    __shared__ float red[128][10];
    int t = threadIdx.x;
    int h = t >> 7, tr = t & 127;
    int r0 = blockIdx.x * 128;
    float acc[10];
#pragma unroll
    for (int o = 0; o < 10; o++) acc[o] = 0.f;

    int kbeg = h * 1792;
    for (int ki = 0; ki < 1792; ki += 32) {
        int k0 = kbeg + ki;
#pragma unroll
        for (int u = 0; u < 4; u++) {
            int idx = u * 128 + tr;
            int row = idx >> 2, q = idx & 3;
            size_t gb = ((size_t)(r0 + row) * K2 + k0) * 2 + q * 16;
            uint4 vh = *(const uint4*)((const char*)Ah + gb);
            uint4 vl = *(const uint4*)((const char*)Al + gb);
            const __nv_bfloat162* hh = (const __nv_bfloat162*)&vh;
            const __nv_bfloat162* ll = (const __nv_bfloat162*)&vl;
            float* dst = &At[h][row][q * 8];
#pragma unroll
            for (int j = 0; j < 4; j++) {
                float2 a = __bfloat1622float2(hh[j]);
                float2 b = __bfloat1622float2(ll[j]);
                dst[j * 2 + 0] = a.x + b.x;
                dst[j * 2 + 1] = a.y + b.y;
            }
        }
        for (int w = tr; w < 320; w += 128)
            Ws[h][w] = W3[(size_t)(k0 + w / 10) * 10 + (w % 10)];
        __syncthreads();
#pragma unroll
        for (int kk = 0; kk < 32; kk++) {
            float a = At[h][tr][kk];
#pragma unroll
            for (int o = 0; o < 10; o++) acc[o] = fmaf(a, Ws[h][kk * 10 + o], acc[o]);
        }
        __syncthreads();
    }
    if (h == 1) {
#pragma unroll
        for (int o = 0; o < 10; o++) red[tr][o] = acc[o];
    }
    __syncthreads();
    if (h == 0) {
#pragma unroll
        for (int o = 0; o < 10; o++) acc[o] += red[tr][o] + bias[o];
        float m = acc[0];
#pragma unroll
        for (int o = 1; o < 10; o++) m = fmaxf(m, acc[o]);
        float s = 0.f;
#pragma unroll
        for (int o = 0; o < 10; o++) s += expf(acc[o] - m);
        float ls = logf(s) + m;
        int row = r0 + tr;
#pragma unroll
        for (int o = 0; o < 10; o++) out[(size_t)row * 10 + o] = acc[o] - ls;
    }
}

// ================= host =================
extern "C" void kernel_launch(void* const* d_in, const int* in_sizes, int n_in,
                              void* d_out, int out_size) {
    const float* x     = (const float*)d_in[0];
    const float* coef1 = (const float*)d_in[1];
    const float* sb1   = (const float*)d_in[2];
    const float* sp1   = (const float*)d_in[3];
    const float* b1    = (const float*)d_in[4];
    const float* coef2 = (const float*)d_in[5];
    const float* sb2   = (const float*)d_in[6];
    const float* sp2   = (const float*)d_in[7];
    const float* b2    = (const float*)d_in[8];
    const float* coef3 = (const float*)d_in[9];
    const float* sb3   = (const float*)d_in[10];
    const float* sp3   = (const float*)d_in[11];
    const float* b3    = (const float*)d_in[12];
    float* out = (float*)d_out;

    float *H0, *H, *W3;
    __nv_bfloat16 *Ah, *Al, *Wh, *Wl;
    cudaGetSymbolAddress((void**)&H0, g_H0);
    cudaGetSymbolAddress((void**)&H,  g_H);
    cudaGetSymbolAddress((void**)&Ah, g_Ah);
    cudaGetSymbolAddress((void**)&Al, g_Al);
    cudaGetSymbolAddress((void**)&Wh, g_Wh);
    cudaGetSymbolAddress((void**)&Wl, g_Wl);
    cudaGetSymbolAddress((void**)&W3, g_W3);

    cudaFuncSetAttribute(gemm_kernel, cudaFuncAttributeMaxDynamicSharedMemorySize, SMEM_GEMM);

    pool_kernel<<<(BATCH * IN1 + 255) / 256, 256>>>(x, H0);

    // ---- layer 1: in=49, K=704 ----
    expand_kernel<<<(BATCH * IN1 + 255) / 256, 256>>>(H0, Ah, Al, IN1, KP1);
    zeropad_kernel<<<(BATCH * (KP1 - 686) + 255) / 256, 256>>>(Ah, Al);
    buildWt_kernel<<<(HID * KP1 + 255) / 256, 256>>>(coef1, sb1, sp1, Wh, Wl, IN1, HID, KP1);
    dim3 g1(HID / 128, BATCH / 128);
    gemm_kernel<<<g1, 256, SMEM_GEMM>>>(Ah, Al, Wh, Wl, b1, H, KP1, HID);

    // ---- layer 2: in=256, K=3584 ----
    expand_kernel<<<(BATCH * HID + 255) / 256, 256>>>(H, Ah, Al, HID, K2);
    buildWt_kernel<<<(HID * K2 + 255) / 256, 256>>>(coef2, sb2, sp2, Wh, Wl, HID, HID, K2);
    gemm_kernel<<<g1, 256, SMEM_GEMM>>>(Ah, Al, Wh, Wl, b2, H, K2, HID);

    // ---- layer 3: K=3584, out=10, fused log_softmax ----
    expand_kernel<<<(BATCH * HID + 255) / 256, 256>>>(H, Ah, Al, HID, K2);
    buildW3_kernel<<<(K2 * OUT3 + 255) / 256, 256>>>(coef3, sb3, sp3, W3);
    layer3_kernel<<<BATCH / 128, 256>>>(Ah, Al, W3, b3, out);
}

// round 6
// speedup vs baseline: 2.4244x; 1.9289x over previous
#include <cuda_runtime.h>
#include <cuda_bf16.h>
#include <cstdint>
#include <math.h>

#define BATCH 8192
#define IN1   49
#define HID   256
#define NCOEF 13
#define KP1   704      // 49*14 = 686, padded to 64-multiple
#define K2    3584     // 256*14
#define OUT3  10

// ================= helpers (baseline PTX only: sm_80-era features) =================
__device__ __forceinline__ uint32_t smem_to_u32(const void* p) {
    uint32_t a;
    asm("{ .reg .u64 t; cvta.to.shared.u64 t, %1; cvt.u32.u64 %0, t; }" : "=r"(a) : "l"(p));
    return a;
}

#define CP16(dst, src) \
    asm volatile("cp.async.cg.shared.global [%0], [%1], 16;" :: "r"(dst), "l"(src) : "memory")
#define CP_COMMIT() asm volatile("cp.async.commit_group;" ::: "memory")
#define CP_WAIT1()  asm volatile("cp.async.wait_group 1;" ::: "memory")
#define CP_WAIT0()  asm volatile("cp.async.wait_group 0;" ::: "memory")

#define LDSM4(r, addr) \
    asm volatile("ldmatrix.sync.aligned.m8n8.x4.shared.b16 {%0,%1,%2,%3}, [%4];" \
        : "=r"((r)[0]), "=r"((r)[1]), "=r"((r)[2]), "=r"((r)[3]) : "r"(addr))

#define MMA_BF16(d, a, b0, b1) \
    asm volatile("mma.sync.aligned.m16n8k16.row.col.f32.bf16.bf16.f32 " \
        "{%0,%1,%2,%3},{%4,%5,%6,%7},{%8,%9},{%0,%1,%2,%3};" \
        : "+f"((d)[0]), "+f"((d)[1]), "+f"((d)[2]), "+f"((d)[3]) \
        : "r"((a)[0]), "r"((a)[1]), "r"((a)[2]), "r"((a)[3]), "r"(b0), "r"(b1))

// ================= scratch =================
__device__ float         g_H [BATCH * HID];
__device__ __nv_bfloat16 g_Ah[(size_t)BATCH * K2];
__device__ __nv_bfloat16 g_Al[(size_t)BATCH * K2];
__device__ __nv_bfloat16 g_Wh1[HID * KP1];
__device__ __nv_bfloat16 g_Wl1[HID * KP1];
__device__ __nv_bfloat16 g_Wh2[HID * K2];
__device__ __nv_bfloat16 g_Wl2[HID * K2];
__device__ float         g_W3[K2 * OUT3];

// ================= shared KAN basis math =================
__device__ __forceinline__ void kan_basis(float xv, float& mishv, float* Bv) {
    float sp = fmaxf(xv, 0.f) + log1pf(expf(-fabsf(xv)));
    mishv = xv * tanhf(sp);
    const float h = 0.4f;
#pragma unroll
    for (int j = 0; j < 16; j++) {
        float t0 = -2.0f + h * (float)(j - 3);
        float t1 = -2.0f + h * (float)(j - 2);
        Bv[j] = (xv >= t0 && xv < t1) ? 1.0f : 0.0f;
    }
#pragma unroll
    for (int d = 1; d <= 3; d++) {
        float inv = 1.0f / (h * (float)d);
#pragma unroll
        for (int j = 0; j < 16 - 3; j++) {
            if (j < 16 - d) {
                float tj   = -2.0f + h * (float)(j - 3);
                float tjd1 = -2.0f + h * (float)(j - 3 + d + 1);
                Bv[j] = (xv - tj) * inv * Bv[j] + (tjd1 - xv) * inv * Bv[j + 1];
            }
        }
        if (d < 3) {
            for (int j = 13; j < 16 - d; j++) {
                float tj   = -2.0f + h * (float)(j - 3);
                float tjd1 = -2.0f + h * (float)(j - 3 + d + 1);
                Bv[j] = (xv - tj) * inv * Bv[j] + (tjd1 - xv) * inv * Bv[j + 1];
            }
        }
    }
}

__device__ __forceinline__ void split_hl(float v, __nv_bfloat16& hi, __nv_bfloat16& lo) {
    hi = __float2bfloat16(v);
    lo = __float2bfloat16(v - __bfloat162float(hi));
}

// ========== expand for in=256 (layers 2/3): 1 batch row per block, smem-staged ==========
__global__ __launch_bounds__(256)
void expand256_kernel(const float* __restrict__ H, __nv_bfloat16* __restrict__ Ah,
                      __nv_bfloat16* __restrict__ Al) {
    __shared__ __nv_bfloat16 sh[K2];
    __shared__ __nv_bfloat16 sl[K2];
    int b = blockIdx.x, i = threadIdx.x;
    float xv = H[b * HID + i];
    float mishv, Bv[16];
    kan_basis(xv, mishv, Bv);
    split_hl(mishv, sh[i], sl[i]);
    int off = HID + i * NCOEF;
#pragma unroll
    for (int g = 0; g < NCOEF; g++) split_hl(Bv[g], sh[off + g], sl[off + g]);
    __syncthreads();

    const uint4* s4h = (const uint4*)sh;
    const uint4* s4l = (const uint4*)sl;
    uint4* oh = (uint4*)(Ah + (size_t)b * K2);
    uint4* ol = (uint4*)(Al + (size_t)b * K2);
    // 3584 bf16 = 7168 B = 448 uint4
#pragma unroll
    for (int u = 0; u < 2; u++) {
        int t = u * 256 + i;
        if (t < 448) { oh[t] = s4h[t]; ol[t] = s4l[t]; }
    }
}

// ========== expand for layer 1: fused pool + basis + pad; 4 batch rows per block ==========
__global__ __launch_bounds__(256)
void expand49_kernel(const float* __restrict__ x, __nv_bfloat16* __restrict__ Ah,
                     __nv_bfloat16* __restrict__ Al) {
    __shared__ __nv_bfloat16 sh[4 * KP1];
    __shared__ __nv_bfloat16 sl[4 * KP1];
    int t = threadIdx.x;
    int b0 = blockIdx.x * 4;
    __nv_bfloat16 z = __float2bfloat16(0.f);

    // zero pad cols [686,704) for all 4 rows: 4*18 = 72 slots
    if (t < 72) {
        int r = t / 18, c = 686 + (t - (t / 18) * 18);
        sh[r * KP1 + c] = z;
        sl[r * KP1 + c] = z;
    }

    if (t < 196) {
        int r = t / 49, i = t - r * 49;
        int b = b0 + r;
        int pr = i / 7, pc = i - pr * 7;
        const float* base = x + (size_t)b * 784 + pr * 4 * 28 + pc * 4;
        float s = 0.f;
#pragma unroll
        for (int k = 0; k < 4; k++) {
            float4 v = *(const float4*)(base + k * 28);
            s += v.x + v.y + v.z + v.w;
        }
        float xv = s * 0.0625f;
        float mishv, Bv[16];
        kan_basis(xv, mishv, Bv);
        __nv_bfloat16* rh = sh + r * KP1;
        __nv_bfloat16* rl = sl + r * KP1;
        split_hl(mishv, rh[i], rl[i]);
        int off = IN1 + i * NCOEF;
#pragma unroll
        for (int g = 0; g < NCOEF; g++) split_hl(Bv[g], rh[off + g], rl[off + g]);
    }
    __syncthreads();

    const uint4* s4h = (const uint4*)sh;
    const uint4* s4l = (const uint4*)sl;
    uint4* oh = (uint4*)(Ah + (size_t)b0 * KP1);
    uint4* ol = (uint4*)(Al + (size_t)b0 * KP1);
    // 4*704 bf16 = 5632 B = 352 uint4
#pragma unroll
    for (int u = 0; u < 2; u++) {
        int w = u * 256 + t;
        if (w < 352) { oh[w] = s4h[w]; ol[w] = s4l[w]; }
    }
}

// ========== pack W^T (N rows, KP cols, K-major) as bf16 hi/lo ==========
__global__ void buildWt_kernel(const float* __restrict__ coef, const float* __restrict__ sb_,
                               const float* __restrict__ sp_, __nv_bfloat16* __restrict__ Wh,
                               __nv_bfloat16* __restrict__ Wl, int in, int out, int KP) {
    int idx = blockIdx.x * blockDim.x + threadIdx.x;
    if (idx >= out * KP) return;
    int n = idx / KP, k = idx - n * KP;
    float v = 0.f;
    if (k < in) {
        v = sb_[k * out + n];
    } else if (k < in * 14) {
        int q = k - in;
        int i = q / 13, g = q - i * 13;
        v = coef[((size_t)i * out + n) * 13 + g] * sp_[i * out + n];
    }
    __nv_bfloat16 hi, lo;
    split_hl(v, hi, lo);
    Wh[idx] = hi;
    Wl[idx] = lo;
}

// ========== pack layer-3 W (K rows, 10 cols) as fp32 ==========
__global__ void buildW3_kernel(const float* __restrict__ coef, const float* __restrict__ sb_,
                               const float* __restrict__ sp_, float* __restrict__ W) {
    int idx = blockIdx.x * blockDim.x + threadIdx.x;
    if (idx >= K2 * OUT3) return;
    int r = idx / OUT3, o = idx - r * OUT3;
    float v;
    if (r < HID) {
        v = sb_[r * OUT3 + o];
    } else {
        int q = r - HID;
        int i = q / 13, g = q - i * 13;
        v = coef[((size_t)i * OUT3 + o) * 13 + g] * sp_[i * OUT3 + o];
    }
    W[idx] = v;
}

// ================= HMMA GEMM: C(M,Nc) = (Ah+Al)(M,K) @ (Wh+Wl)^T + bias =================
// 128x128 tile, K-chunk 32 bf16, cp.async double buffer, mma.sync m16n8k16, 3-term split.
#define ASTRIDE     80                 // 64B data + 16B pad: conflict-free ldmatrix
#define MAT_BYTES   (128 * ASTRIDE)    // 10240
#define STAGE_BYTES (4 * MAT_BYTES)    // 40960
#define SMEM_GEMM   (2 * STAGE_BYTES + 512)

__global__ __launch_bounds__(256)
void gemm_kernel(const __nv_bfloat16* __restrict__ Ah, const __nv_bfloat16* __restrict__ Al,
                 const __nv_bfloat16* __restrict__ Wh, const __nv_bfloat16* __restrict__ Wl,
                 const float* __restrict__ bias, float* __restrict__ C, int K, int Nc) {
    extern __shared__ char smem[];
    uint32_t sbase = smem_to_u32(smem);
    float* bsm = (float*)(smem + 2 * STAGE_BYTES);
    int tid = threadIdx.x, lane = tid & 31, wid = tid >> 5;
    int bm = blockIdx.y * 128, bn = blockIdx.x * 128;
    if (tid < 128) bsm[tid] = bias[bn + tid];

    const size_t strideA = (size_t)K * 2;   // bytes per row
    const char* pAh = (const char*)Ah;
    const char* pAl = (const char*)Al;
    const char* pWh = (const char*)Wh;
    const char* pWl = (const char*)Wl;

    float acc[4][4][4];
#pragma unroll
    for (int i = 0; i < 4; i++)
#pragma unroll
        for (int j = 0; j < 4; j++)
#pragma unroll
            for (int q = 0; q < 4; q++) acc[i][j][q] = 0.f;

    // warp tile: 64 (M) x 32 (N)
    int wm = (wid & 1) * 64, wn = (wid >> 1) * 32;
    int a_row = lane & 15, a_hi = lane >> 4;
    int bg = lane >> 3;
    int b_row = ((bg >> 1) << 3) + (lane & 7);
    int b_hi = bg & 1;

    int nch = K >> 5;

#define LOAD_CHUNK(stage, c) do { \
        size_t kb = (size_t)(c) * 64; \
        uint32_t sst = sbase + (stage) * STAGE_BYTES; \
        _Pragma("unroll") \
        for (int u = 0; u < 2; u++) { \
            int idx = u * 256 + tid; \
            int row = idx >> 2, ch = idx & 3; \
            uint32_t soff = row * ASTRIDE + ch * 16; \
            size_t ga = (size_t)(bm + row) * strideA + kb + ch * 16; \
            size_t gb = (size_t)(bn + row) * strideA + kb + ch * 16; \
            CP16(sst + soff,                 pAh + ga); \
            CP16(sst + MAT_BYTES + soff,     pAl + ga); \
            CP16(sst + 2 * MAT_BYTES + soff, pWh + gb); \
            CP16(sst + 3 * MAT_BYTES + soff, pWl + gb); \
        } \
    } while (0)

    LOAD_CHUNK(0, 0);
    CP_COMMIT();

    for (int c = 0; c < nch; c++) {
        if (c + 1 < nch) {
            LOAD_CHUNK((c + 1) & 1, c + 1);
            CP_COMMIT();
            CP_WAIT1();
        } else {
            CP_WAIT0();
        }
        __syncthreads();

        uint32_t base = sbase + (c & 1) * STAGE_BYTES;
        uint32_t aAh = base, aAl = base + MAT_BYTES;
        uint32_t aBh = base + 2 * MAT_BYTES, aBl = base + 3 * MAT_BYTES;

#pragma unroll
        for (int kk = 0; kk < 2; kk++) {
            int kch = kk * 2;
            uint32_t ahf[4][4], alf[4][4], bhf[2][4], blf[2][4];
#pragma unroll
            for (int mt = 0; mt < 4; mt++) {
                uint32_t ao = (uint32_t)(wm + mt * 16 + a_row) * ASTRIDE + (kch + a_hi) * 16;
                LDSM4(ahf[mt], aAh + ao);
                LDSM4(alf[mt], aAl + ao);
            }
#pragma unroll
            for (int np = 0; np < 2; np++) {
                uint32_t bo = (uint32_t)(wn + np * 16 + b_row) * ASTRIDE + (kch + b_hi) * 16;
                LDSM4(bhf[np], aBh + bo);
                LDSM4(blf[np], aBl + bo);
            }
#pragma unroll
            for (int mt = 0; mt < 4; mt++)
#pragma unroll
                for (int nt = 0; nt < 4; nt++) {
                    int np = nt >> 1, s = (nt & 1) * 2;
                    MMA_BF16(acc[mt][nt], ahf[mt], bhf[np][s], bhf[np][s + 1]);
                    MMA_BF16(acc[mt][nt], ahf[mt], blf[np][s], blf[np][s + 1]);
                    MMA_BF16(acc[mt][nt], alf[mt], bhf[np][s], bhf[np][s + 1]);
                }
        }
        __syncthreads();
    }
#undef LOAD_CHUNK

#pragma unroll
    for (int mt = 0; mt < 4; mt++) {
        int r0 = bm + wm + mt * 16 + (lane >> 2);
#pragma unroll
        for (int nt = 0; nt < 4; nt++) {
            int cl = wn + nt * 8 + (lane & 3) * 2;
            float bz0 = bsm[cl], bz1 = bsm[cl + 1];
            float2 v0, v1;
            v0.x = acc[mt][nt][0] + bz0;  v0.y = acc[mt][nt][1] + bz1;
            v1.x = acc[mt][nt][2] + bz0;  v1.y = acc[mt][nt][3] + bz1;
            *(float2*)(C + (size_t)r0 * Nc + bn + cl)       = v0;
            *(float2*)(C + (size_t)(r0 + 8) * Nc + bn + cl) = v1;
        }
    }
}

// ================= layer3: (B,3584)@(3584,10) + bias, fused log_softmax, split-K =================
__global__ __launch_bounds__(256)
void layer3_kernel(const __nv_bfloat16* __restrict__ Ah, const __nv_bfloat16* __restrict__ Al,
                   const float* __restrict__ W3, const float* __restrict__ bias,
                   float* __restrict__ out) {
    __shared__ float At[2][128][33];
    __shared__ float Ws[2][320];
    __shared__ float red[128][10];
    int t = threadIdx.x;
    int h = t >> 7, tr = t & 127;
    int r0 = blockIdx.x * 128;
    float acc[10];
#pragma unroll
    for (int o = 0; o < 10; o++) acc[o] = 0.f;

    int kbeg = h * 1792;
    for (int ki = 0; ki < 1792; ki += 32) {
        int k0 = kbeg + ki;
#pragma unroll
        for (int u = 0; u < 4; u++) {
            int idx = u * 128 + tr;
            int row = idx >> 2, q = idx & 3;
            size_t gb = ((size_t)(r0 + row) * K2 + k0) * 2 + q * 16;
            uint4 vh = *(const uint4*)((const char*)Ah + gb);
            uint4 vl = *(const uint4*)((const char*)Al + gb);
            const __nv_bfloat162* hh = (const __nv_bfloat162*)&vh;
            const __nv_bfloat162* ll = (const __nv_bfloat162*)&vl;
            float* dst = &At[h][row][q * 8];
#pragma unroll
            for (int j = 0; j < 4; j++) {
                float2 a = __bfloat1622float2(hh[j]);
                float2 b = __bfloat1622float2(ll[j]);
                dst[j * 2 + 0] = a.x + b.x;
                dst[j * 2 + 1] = a.y + b.y;
            }
        }
        for (int w = tr; w < 320; w += 128)
            Ws[h][w] = W3[(size_t)(k0 + w / 10) * 10 + (w % 10)];
        __syncthreads();
#pragma unroll
        for (int kk = 0; kk < 32; kk++) {
            float a = At[h][tr][kk];
#pragma unroll
            for (int o = 0; o < 10; o++) acc[o] = fmaf(a, Ws[h][kk * 10 + o], acc[o]);
        }
        __syncthreads();
    }
    if (h == 1) {
#pragma unroll
        for (int o = 0; o < 10; o++) red[tr][o] = acc[o];
    }
    __syncthreads();
    if (h == 0) {
#pragma unroll
        for (int o = 0; o < 10; o++) acc[o] += red[tr][o] + bias[o];
        float m = acc[0];
#pragma unroll
        for (int o = 1; o < 10; o++) m = fmaxf(m, acc[o]);
        float s = 0.f;
#pragma unroll
        for (int o = 0; o < 10; o++) s += expf(acc[o] - m);
        float ls = logf(s) + m;
        int row = r0 + tr;
#pragma unroll
        for (int o = 0; o < 10; o++) out[(size_t)row * 10 + o] = acc[o] - ls;
    }
}

// ================= host =================
extern "C" void kernel_launch(void* const* d_in, const int* in_sizes, int n_in,
                              void* d_out, int out_size) {
    const float* x     = (const float*)d_in[0];
    const float* coef1 = (const float*)d_in[1];
    const float* sb1   = (const float*)d_in[2];
    const float* sp1   = (const float*)d_in[3];
    const float* b1    = (const float*)d_in[4];
    const float* coef2 = (const float*)d_in[5];
    const float* sb2   = (const float*)d_in[6];
    const float* sp2   = (const float*)d_in[7];
    const float* b2    = (const float*)d_in[8];
    const float* coef3 = (const float*)d_in[9];
    const float* sb3   = (const float*)d_in[10];
    const float* sp3   = (const float*)d_in[11];
    const float* b3    = (const float*)d_in[12];
    float* out = (float*)d_out;

    float *H, *W3;
    __nv_bfloat16 *Ah, *Al, *Wh1, *Wl1, *Wh2, *Wl2;
    cudaGetSymbolAddress((void**)&H,   g_H);
    cudaGetSymbolAddress((void**)&Ah,  g_Ah);
    cudaGetSymbolAddress((void**)&Al,  g_Al);
    cudaGetSymbolAddress((void**)&Wh1, g_Wh1);
    cudaGetSymbolAddress((void**)&Wl1, g_Wl1);
    cudaGetSymbolAddress((void**)&Wh2, g_Wh2);
    cudaGetSymbolAddress((void**)&Wl2, g_Wl2);
    cudaGetSymbolAddress((void**)&W3,  g_W3);

    cudaFuncSetAttribute(gemm_kernel, cudaFuncAttributeMaxDynamicSharedMemorySize, SMEM_GEMM);

    dim3 g1(HID / 128, BATCH / 128);

    // launch order chosen so ncu's fixed skip lands on a gemm (our #3 or #5)
    buildWt_kernel<<<(HID * KP1 + 255) / 256, 256>>>(coef1, sb1, sp1, Wh1, Wl1, IN1, HID, KP1); // 0
    buildWt_kernel<<<(HID * K2 + 255) / 256, 256>>>(coef2, sb2, sp2, Wh2, Wl2, HID, HID, K2);   // 1
    expand49_kernel<<<BATCH / 4, 256>>>(x, Ah, Al);                                              // 2
    gemm_kernel<<<g1, 256, SMEM_GEMM>>>(Ah, Al, Wh1, Wl1, b1, H, KP1, HID);                      // 3
    expand256_kernel<<<BATCH, 256>>>(H, Ah, Al);                                                 // 4
    gemm_kernel<<<g1, 256, SMEM_GEMM>>>(Ah, Al, Wh2, Wl2, b2, H, K2, HID);                       // 5
    expand256_kernel<<<BATCH, 256>>>(H, Ah, Al);                                                 // 6
    buildW3_kernel<<<(K2 * OUT3 + 255) / 256, 256>>>(coef3, sb3, sp3, W3);                       // 7
    layer3_kernel<<<BATCH / 128, 256>>>(Ah, Al, W3, b3, out);                                    // 8
}